// round 11
// baseline (speedup 1.0000x reference)
#include <cuda_runtime.h>
#include <cuda_bf16.h>
#include <cstdint>

// Problem constants (fixed by reference setup_inputs)
#define BB 8
#define SS 2048
#define HH 1024
#define NTOK (BB * SS)                 // 16384
#define BSS ((long long)BB * SS * SS)  // 33,554,432

// Scratch: per-token combined scores. Non-candidates encoded as -1e30 so that
// pair_score = sS + sE + bm is guaranteed <= 0 -> invalid -> outputs 0.
__device__ float g_sS[NTOK];
__device__ float g_sE[NTOK];

// ---------------------------------------------------------------------------
// Phase 1: per-token logits + scalar scores. TWO tokens per warp, loads
// issued per-iteration (2 LDG + 4 LDS each iter) so weight LDS traffic is
// amortized across both tokens without front-batch register pressure.
// Weights staged in shared as SoA -> conflict-free LDS.128.
// ---------------------------------------------------------------------------
__global__ __launch_bounds__(256) void token_kernel(
    const float* __restrict__ rep,   // (B,S,H)
    const int*   __restrict__ mask,  // (B,S)
    const float* __restrict__ Ws,    // (H,2)
    const float* __restrict__ bs,    // (2,)
    const float* __restrict__ We,    // (H,2)
    const float* __restrict__ be,    // (2,)
    const float* __restrict__ Wm)    // (4,1)
{
    __shared__ float s_w0[HH];  // Ws[:,0]
    __shared__ float s_w1[HH];  // Ws[:,1]
    __shared__ float s_w2[HH];  // We[:,0]
    __shared__ float s_w3[HH];  // We[:,1]
    for (int h = threadIdx.x; h < HH; h += blockDim.x) {
        s_w0[h] = Ws[2 * h];
        s_w1[h] = Ws[2 * h + 1];
        s_w2[h] = We[2 * h];
        s_w3[h] = We[2 * h + 1];
    }
    __syncthreads();

    const int warp = threadIdx.x >> 5;
    const int lane = threadIdx.x & 31;
    // 1024 blocks * 8 warps * 2 tokens = 16384 tokens
    const int tA = blockIdx.x * 16 + warp * 2;
    const int tB = tA + 1;

    const float4* __restrict__ rA4 =
        reinterpret_cast<const float4*>(rep + (size_t)tA * HH);
    const float4* __restrict__ rB4 =
        reinterpret_cast<const float4*>(rep + (size_t)tB * HH);

    float as0 = 0.f, as1 = 0.f, ae0 = 0.f, ae1 = 0.f;
    float xs0 = 0.f, xs1 = 0.f, xe0 = 0.f, xe1 = 0.f;
#pragma unroll
    for (int it = 0; it < HH / 128; ++it) {   // 8 iterations
        const int idx = it * 32 + lane;
        const float4 a  = __ldcs(&rA4[idx]);
        const float4 x  = __ldcs(&rB4[idx]);
        const float4 w0 = *reinterpret_cast<const float4*>(&s_w0[idx * 4]);
        const float4 w1 = *reinterpret_cast<const float4*>(&s_w1[idx * 4]);
        const float4 w2 = *reinterpret_cast<const float4*>(&s_w2[idx * 4]);
        const float4 w3 = *reinterpret_cast<const float4*>(&s_w3[idx * 4]);
        as0 += a.x * w0.x + a.y * w0.y + a.z * w0.z + a.w * w0.w;
        as1 += a.x * w1.x + a.y * w1.y + a.z * w1.z + a.w * w1.w;
        ae0 += a.x * w2.x + a.y * w2.y + a.z * w2.z + a.w * w2.w;
        ae1 += a.x * w3.x + a.y * w3.y + a.z * w3.z + a.w * w3.w;
        xs0 += x.x * w0.x + x.y * w0.y + x.z * w0.z + x.w * w0.w;
        xs1 += x.x * w1.x + x.y * w1.y + x.z * w1.z + x.w * w1.w;
        xe0 += x.x * w2.x + x.y * w2.y + x.z * w2.z + x.w * w2.w;
        xe1 += x.x * w3.x + x.y * w3.y + x.z * w3.z + x.w * w3.w;
    }
#pragma unroll
    for (int off = 16; off > 0; off >>= 1) {
        as0 += __shfl_down_sync(0xFFFFFFFFu, as0, off);
        as1 += __shfl_down_sync(0xFFFFFFFFu, as1, off);
        ae0 += __shfl_down_sync(0xFFFFFFFFu, ae0, off);
        ae1 += __shfl_down_sync(0xFFFFFFFFu, ae1, off);
        xs0 += __shfl_down_sync(0xFFFFFFFFu, xs0, off);
        xs1 += __shfl_down_sync(0xFFFFFFFFu, xs1, off);
        xe0 += __shfl_down_sync(0xFFFFFFFFu, xe0, off);
        xe1 += __shfl_down_sync(0xFFFFFFFFu, xe1, off);
    }
    if (lane == 0) {
        const float wm0 = Wm[0], wm1 = Wm[1], wm2 = Wm[2], wm3 = Wm[3];
        const float c0 = bs[0], c1 = bs[1], c2 = be[0], c3 = be[1];
        {
            const float s0 = as0 + c0, s1 = as1 + c1;
            const float e0 = ae0 + c2, e1 = ae1 + c3;
            const bool m = (mask[tA] != 0);
            g_sS[tA] = (m && s0 <= s1) ? (s0 * wm0 + s1 * wm1) : -1e30f;
            g_sE[tA] = (m && e0 <= e1) ? (e0 * wm2 + e1 * wm3) : -1e30f;
        }
        {
            const float s0 = xs0 + c0, s1 = xs1 + c1;
            const float e0 = xe0 + c2, e1 = xe1 + c3;
            const bool m = (mask[tB] != 0);
            g_sS[tB] = (m && s0 <= s1) ? (s0 * wm0 + s1 * wm1) : -1e30f;
            g_sE[tB] = (m && e0 <= e1) ? (e0 * wm2 + e1 * wm3) : -1e30f;
        }
    }
}

// ---------------------------------------------------------------------------
// Phase 2: fill the (B,S,S) pair grid. Pure store-bandwidth kernel.
// Monolithic grid, 4 el/thread, plain float4 stores (measured-best R1 form;
// DO NOT widen: 8 el/thread splits sectors across STG.128 -> partial-sector
// DRAM writes, measured regression in R2).
// ---------------------------------------------------------------------------
__global__ __launch_bounds__(256) void pair_kernel(
    float* __restrict__ out_valid,
    float* __restrict__ out_score,
    const float* __restrict__ bm)
{
    const long long tid = (long long)blockIdx.x * blockDim.x + threadIdx.x;
    const int  j   = (int)(tid & (SS / 4 - 1)) * 4;  // 512 threads per row
    const long long row = tid >> 9;                  // row = b*S + i
    const int  i   = (int)(row & (SS - 1));

    const float sSv = g_sS[row];
    const long long ebase = row - i;                 // b*S
    const float4 ev = *reinterpret_cast<const float4*>(&g_sE[ebase + j]);
    const float bmv = bm[0];

    float p0 = sSv + ev.x + bmv;
    float p1 = sSv + ev.y + bmv;
    float p2 = sSv + ev.z + bmv;
    float p3 = sSv + ev.w + bmv;

    const bool v0 = (i <= j + 0) && (p0 > 0.f);
    const bool v1 = (i <= j + 1) && (p1 > 0.f);
    const bool v2 = (i <= j + 2) && (p2 > 0.f);
    const bool v3 = (i <= j + 3) && (p3 > 0.f);

    float4 vo, so;
    vo.x = v0 ? 1.f : 0.f;  so.x = v0 ? p0 : 0.f;
    vo.y = v1 ? 1.f : 0.f;  so.y = v1 ? p1 : 0.f;
    vo.z = v2 ? 1.f : 0.f;  so.z = v2 ? p2 : 0.f;
    vo.w = v3 ? 1.f : 0.f;  so.w = v3 ? p3 : 0.f;

    const long long o = tid * 4;
    *reinterpret_cast<float4*>(out_valid + o) = vo;
    *reinterpret_cast<float4*>(out_score + o) = so;
}

extern "C" void kernel_launch(void* const* d_in, const int* in_sizes, int n_in,
                              void* d_out, int out_size)
{
    const float* rep  = (const float*)d_in[0];
    const int*   mask = (const int*)  d_in[1];
    const float* Ws   = (const float*)d_in[2];
    const float* bs   = (const float*)d_in[3];
    const float* We   = (const float*)d_in[4];
    const float* be   = (const float*)d_in[5];
    const float* Wm   = (const float*)d_in[6];
    const float* bm   = (const float*)d_in[7];

    float* out_valid = (float*)d_out;
    float* out_score = out_valid + BSS;

    // Phase 1: 16384 tokens, two per warp, 8 warps per block.
    token_kernel<<<NTOK / 16, 256>>>(rep, mask, Ws, bs, We, be, Wm);

    // Phase 2: BSS/4 threads, monolithic grid.
    const long long nthreads = BSS / 4;
    pair_kernel<<<(unsigned)(nthreads / 256), 256>>>(out_valid, out_score, bm);
}